// round 1
// baseline (speedup 1.0000x reference)
#include <cuda_runtime.h>
#include <math.h>

// Problem shapes (fixed by setup_inputs): B=8, C=256, H=W=256, 4x4 blocks of 64x64.
#define BB 8
#define CC 256
#define HWF4 16384            // (H*W)/4 in float4 units per channel
#define NBLK 32768            // B * 4 * 4 * C block-channels
#define BLK_N 4096.0f         // elements per block (64*64)
#define N_INV (1.0f/4095.0f)  // 1/(bh*bw - 1)
#define E_LAMBDA 1e-4f
#define TOTAL_ELEMS 536870912.0f

// Scratch (device globals; no allocations allowed)
__device__ float2 g_sums[NBLK];    // (sum x, sum x^2) per block-channel
__device__ float2 g_muinv[NBLK];   // (mu, inv_denom) per block-channel
__device__ float  g_s[NBLK];       // mean(eb) per block-channel
__device__ float  g_gate[NBLK];    // SE gate per block-channel

__device__ __forceinline__ float warpsum(float v) {
    #pragma unroll
    for (int o = 16; o; o >>= 1) v += __shfl_xor_sync(0xffffffffu, v, o);
    return v;
}

// Decode block-channel id -> float4 base offset of its 64x64 tile
__device__ __forceinline__ int blk_base_f4(int idx, int& c_out) {
    int c  = idx & 255;
    int t3 = idx >> 8;          // b*16 + i*4 + j
    int j  = t3 & 3;
    int i  = (t3 >> 2) & 3;
    int b  = t3 >> 4;
    c_out = c;
    // float4 units: channel stride 16384, row stride 64, col-block stride 16
    return (b * CC + c) * HWF4 + (i * 64) * 64 + j * 16;
}

// ---------------- K1: per-block sum / sumsq -----------------
__global__ void k1_stats(const float4* __restrict__ x) {
    int idx = blockIdx.x;
    int c;
    int base = blk_base_f4(idx, c);
    int t = threadIdx.x;               // 256 threads
    float s = 0.f, s2 = 0.f;
    #pragma unroll
    for (int it = 0; it < 4; it++) {
        int q  = it * 256 + t;         // 0..1023 float4 slots
        int r  = q >> 4;               // row 0..63
        int qq = q & 15;               // float4 within row
        float4 v = x[base + r * 64 + qq];
        s  += v.x + v.y + v.z + v.w;
        s2 += v.x * v.x + v.y * v.y + v.z * v.z + v.w * v.w;
    }
    __shared__ float sh[8], sh2[8];
    int w = t >> 5, lane = t & 31;
    s = warpsum(s); s2 = warpsum(s2);
    if (lane == 0) { sh[w] = s; sh2[w] = s2; }
    __syncthreads();
    if (t == 0) {
        float a = 0.f, b2 = 0.f;
        #pragma unroll
        for (int k = 0; k < 8; k++) { a += sh[k]; b2 += sh2[k]; }
        g_sums[idx] = make_float2(a, b2);
    }
}

// ---------------- K2: global lambda + per-block (mu, inv) ----
__global__ void k2_prep() {
    __shared__ float red[32];
    int t = threadIdx.x;               // 1024 threads
    float s = 0.f;
    for (int q = t; q < NBLK; q += 1024) s += g_sums[q].x;
    s = warpsum(s);
    if ((t & 31) == 0) red[t >> 5] = s;
    __syncthreads();
    if (t < 32) {
        float v = red[t];
        v = warpsum(v);
        if (t == 0) red[0] = v;
    }
    __syncthreads();
    float mean = red[0] / TOTAL_ELEMS;
    float lam  = E_LAMBDA * log1pf(fabsf(mean));
    for (int q = t; q < NBLK; q += 1024) {
        float2 ss = g_sums[q];
        float mu  = ss.x * (1.0f / BLK_N);
        float sd2 = ss.y - BLK_N * mu * mu;      // sum of (x-mu)^2
        float inv = 1.0f / (4.0f * (sd2 * N_INV + lam));
        g_muinv[q] = make_float2(mu, inv);
    }
}

__device__ __forceinline__ float eb_elem(float a, float mu, float inv) {
    float d = a - mu;
    float y = d * d * inv + 0.5f;
    return a * (1.0f / (1.0f + __expf(-y)));
}

// ---------------- K3: sum(eb) per block-channel --------------
__global__ void k3_ebsum(const float4* __restrict__ x) {
    int idx = blockIdx.x;
    int c;
    int base = blk_base_f4(idx, c);
    float2 mi = g_muinv[idx];
    int t = threadIdx.x;
    float s = 0.f;
    #pragma unroll
    for (int it = 0; it < 4; it++) {
        int q  = it * 256 + t;
        int r  = q >> 4;
        int qq = q & 15;
        float4 v = x[base + r * 64 + qq];
        s += eb_elem(v.x, mi.x, mi.y) + eb_elem(v.y, mi.x, mi.y)
           + eb_elem(v.z, mi.x, mi.y) + eb_elem(v.w, mi.x, mi.y);
    }
    __shared__ float sh[8];
    int w = t >> 5, lane = t & 31;
    s = warpsum(s);
    if (lane == 0) sh[w] = s;
    __syncthreads();
    if (t == 0) {
        float a = 0.f;
        #pragma unroll
        for (int k = 0; k < 8; k++) a += sh[k];
        g_s[idx] = a * (1.0f / BLK_N);
    }
}

// ---------------- K4: SE MLP per (b,i,j) ---------------------
__global__ void k4_se(const float* __restrict__ w1, const float* __restrict__ w2) {
    __shared__ float s_s[256];
    __shared__ float s_h[16];
    int g    = blockIdx.x;             // 0..127 = (b,i,j)
    int t    = threadIdx.x;            // 256 threads
    int base = g * 256;
    s_s[t] = g_s[base + t];
    __syncthreads();
    int w = t >> 5, lane = t & 31;
    // 8 warps x 2 rows each = 16 hidden units
    #pragma unroll
    for (int rr = 0; rr < 2; rr++) {
        int r = w * 2 + rr;
        float acc = 0.f;
        #pragma unroll
        for (int k = 0; k < 8; k++) {
            int cidx = lane + k * 32;
            acc += w1[r * 256 + cidx] * s_s[cidx];
        }
        acc = warpsum(acc);
        if (lane == 0) s_h[r] = fmaxf(acc, 0.f);
    }
    __syncthreads();
    float acc = 0.f;
    #pragma unroll
    for (int r = 0; r < 16; r++) acc += w2[t * 16 + r] * s_h[r];
    g_gate[base + t] = 1.0f / (1.0f + __expf(-acc));
}

// ---------------- K5: out = eb * gate ------------------------
__global__ void k5_out(const float4* __restrict__ x, float4* __restrict__ out) {
    int idx = blockIdx.x;
    int c;
    int base = blk_base_f4(idx, c);
    float2 mi  = g_muinv[idx];
    float gate = g_gate[idx];
    int t = threadIdx.x;
    #pragma unroll
    for (int it = 0; it < 4; it++) {
        int q  = it * 256 + t;
        int r  = q >> 4;
        int qq = q & 15;
        int a  = base + r * 64 + qq;
        float4 v = x[a];
        float4 o;
        o.x = eb_elem(v.x, mi.x, mi.y) * gate;
        o.y = eb_elem(v.y, mi.x, mi.y) * gate;
        o.z = eb_elem(v.z, mi.x, mi.y) * gate;
        o.w = eb_elem(v.w, mi.x, mi.y) * gate;
        out[a] = o;
    }
}

extern "C" void kernel_launch(void* const* d_in, const int* in_sizes, int n_in,
                              void* d_out, int out_size) {
    const float4* x  = (const float4*)d_in[0];
    const float*  w1 = (const float*)d_in[1];
    const float*  w2 = (const float*)d_in[2];
    float4* out = (float4*)d_out;

    k1_stats<<<NBLK, 256>>>(x);
    k2_prep<<<1, 1024>>>();
    k3_ebsum<<<NBLK, 256>>>(x);
    k4_se<<<128, 256>>>(w1, w2);
    k5_out<<<NBLK, 256>>>(x, out);
}